// round 14
// baseline (speedup 1.0000x reference)
#include <cuda_runtime.h>
#include <math.h>
#include <float.h>
#include <stdint.h>

#define EPSV 1e-6f
#define SCALEV 0.125f

typedef unsigned long long u64;

__device__ __forceinline__ u64 fma2(u64 a, u64 b, u64 c){ u64 d; asm("fma.rn.f32x2 %0,%1,%2,%3;":"=l"(d):"l"(a),"l"(b),"l"(c)); return d; }
__device__ __forceinline__ u64 add2(u64 a, u64 b){ u64 d; asm("add.rn.f32x2 %0,%1,%2;":"=l"(d):"l"(a),"l"(b)); return d; }
__device__ __forceinline__ float hadd2(u64 a){ float x,y; asm("mov.b64 {%0,%1},%2;":"=f"(x),"=f"(y):"l"(a)); return x+y; }
__device__ __forceinline__ void cp16(uint32_t dst, const void* src){
    asm volatile("cp.async.cg.shared.global [%0], [%1], 16;" :: "r"(dst), "l"(src));
}

__device__ float d_gp[16 * 64];
__device__ float d_sgp[16];
__device__ float d_ck[16];

__global__ void setup_kernel(const float* __restrict__ prot,
                             const float* __restrict__ gamma,
                             const float* __restrict__ beta)
{
    int w = threadIdx.x >> 5;
    int l = threadIdx.x & 31;
    if (w >= 16) return;
    const float* g0 = gamma;       const float* b0 = beta;
    const float* g1 = gamma + 64;  const float* b1 = beta + 64;

    float p0 = prot[w * 64 + l];
    float p1 = prot[w * 64 + l + 32];
    float s = p0 + p1, q = p0 * p0 + p1 * p1;
    #pragma unroll
    for (int m = 16; m; m >>= 1) {
        s += __shfl_xor_sync(~0u, s, m);
        q += __shfl_xor_sync(~0u, q, m);
    }
    float mean = s * (1.f / 64.f);
    float var  = q * (1.f / 64.f) - mean * mean;
    float r    = rsqrtf(var + EPSV);
    float pn0 = (p0 - mean) * r * g1[l]      + b1[l];
    float pn1 = (p1 - mean) * r * g1[l + 32] + b1[l + 32];
    float gp0 = g0[l] * pn0;
    float gp1 = g0[l + 32] * pn1;
    d_gp[w * 64 + l]      = gp0;
    d_gp[w * 64 + l + 32] = gp1;
    float sg  = gp0 + gp1;
    float ckp = b0[l] * pn0 + b0[l + 32] * pn1;
    #pragma unroll
    for (int m = 16; m; m >>= 1) {
        sg  += __shfl_xor_sync(~0u, sg, m);
        ckp += __shfl_xor_sync(~0u, ckp, m);
    }
    if (l == 0) { d_sgp[w] = sg; d_ck[w] = ckp; }
}

// Thread roles:
//   staging/stats/GEMM/softmaxK: row = tid>>2, quarter sc0 = (tid&3)*16,
//                                k-quad k4 = (tid&3)*4  (stats live in regs)
//   aggregation: dg4/kg4/tcb
__global__ __launch_bounds__(256, 4)
void dse_main_kernel(const float* __restrict__ z,
                     const float* __restrict__ alphas,
                     const float* __restrict__ b_bias,
                     const float* __restrict__ W,
                     const float* __restrict__ gamma,
                     const float* __restrict__ beta,
                     const float* __restrict__ beta_seq,
                     float* __restrict__ out)
{
    __shared__ __align__(16) float  z_s[2][64 * 68];   // 34816 B
    __shared__ __align__(16) float2 sw2[64 * 18];      //  9216 B (stride 18)
    __shared__ __align__(16) float  gp_s[16 * 68];     //  4352 B
    __shared__ __align__(16) float  sm_uq[64];         // q then u (warp0 only)
    __shared__ float sm_S;

    const int tid  = threadIdx.x;
    const int lane = tid & 31;
    const int wid  = tid >> 5;
    const int b    = blockIdx.x;
    const size_t zb = (size_t)b * (1024 * 64);

    const int srow = tid >> 2;
    const int sc0  = (tid & 3) * 16;
    const int k4   = (tid & 3) * 4;

    const uint32_t zshA = (uint32_t)__cvta_generic_to_shared(&z_s[0][srow * 68 + sc0]);
    const uint32_t zshB = (uint32_t)__cvta_generic_to_shared(&z_s[1][srow * 68 + sc0]);
    const float* gsrc = z + zb + (size_t)srow * 64 + sc0;
    const float* asrc = alphas + (size_t)srow * 64 + sc0;

    // tile 0 fetch
    #pragma unroll
    for (int j = 0; j < 4; j++) cp16(zshA + j * 16, gsrc + 4 * j);
    asm volatile("cp.async.commit_group;" ::: "memory");

    // per-thread prototype constants for its 4 ks
    float sgp4[4], ck4[4];
    #pragma unroll
    for (int j = 0; j < 4; j++) { sgp4[j] = d_sgp[k4 + j]; ck4[j] = d_ck[k4 + j]; }

    // ---- prologue ----
    if (wid == 0) {
        const float* g3 = gamma + 3 * 64;
        const float* b3 = beta  + 3 * 64;
        const float* g2 = gamma + 2 * 64;
        const int d1 = lane, d2 = lane + 32;
        float x1 = alphas[1023 * 64 + d1] + z[zb + 1023 * 64 + d1] + b_bias[d1];
        float x2 = alphas[1023 * 64 + d2] + z[zb + 1023 * 64 + d2] + b_bias[d2];
        float s = x1 + x2, sq = x1 * x1 + x2 * x2;
        #pragma unroll
        for (int m = 16; m; m >>= 1) {
            s  += __shfl_xor_sync(~0u, s,  m);
            sq += __shfl_xor_sync(~0u, sq, m);
        }
        float mean = s * (1.f / 64.f);
        float var  = sq * (1.f / 64.f) - mean * mean;
        float r    = rsqrtf(var + EPSV);
        float q1 = (x1 - mean) * r * g3[d1] + b3[d1];
        float q2 = (x2 - mean) * r * g3[d2] + b3[d2];
        sm_uq[d1] = q1; sm_uq[d2] = q2;
        __syncwarp();
        float wq1 = 0.f, wq2 = 0.f;
        #pragma unroll 4
        for (int e4 = 0; e4 < 16; e4++) {
            float4 qv = *(const float4*)&sm_uq[e4 * 4];
            float4 w1 = *(const float4*)(W + d1 * 64 + e4 * 4);
            float4 w2 = *(const float4*)(W + d2 * 64 + e4 * 4);
            wq1 += w1.x * qv.x + w1.y * qv.y + w1.z * qv.z + w1.w * qv.w;
            wq2 += w2.x * qv.x + w2.y * qv.y + w2.z * qv.z + w2.w * qv.w;
        }
        __syncwarp();   // all lanes done reading q before overwriting with u
        float u1 = g2[d1] * (q1 + wq1);
        float u2 = g2[d2] * (q2 + wq2);
        sm_uq[d1] = u1; sm_uq[d2] = u2;
    } else {
        for (int i = tid - 32; i < 256; i += 224) {
            int row = i >> 4, c4 = (i & 15) * 4;
            *(float4*)&gp_s[row * 68 + c4] = *(const float4*)&d_gp[row * 64 + c4];
        }
        if (tid == 32) sm_S = 0.f;
    }
    __syncthreads();

    // su = sum(u): 16 x 4-float reads (FIXED: stride 4 floats, was 8)
    float su;
    {
        u64 s2 = 0;
        #pragma unroll
        for (int j = 0; j < 16; j++) {
            ulonglong2 uw = *(const ulonglong2*)&sm_uq[j * 4];
            s2 = add2(s2, uw.x); s2 = add2(s2, uw.y);
        }
        su = hadd2(s2);
    }

    // aggregation mapping
    const int idx  = tid & 63;
    const int dg4  = (idx & 15) * 4;
    const int kg4  = (idx >> 4) * 4;
    const int tcb  = (tid >> 6) * 16;

    u64 acc[4][2] = {{0,0},{0,0},{0,0},{0,0}};
    float S_part = 0.f;

    #pragma unroll 1
    for (int tile = 0; tile < 16; tile++) {
        const int buf = tile & 1;
        const float* zc = z_s[buf];

        // alphas loads (issued before cp wait)
        const float* ar = asrc + (size_t)tile * 4096;
        ulonglong2 aw0 = *(const ulonglong2*)(ar);
        ulonglong2 aw1 = *(const ulonglong2*)(ar + 4);
        ulonglong2 aw2 = *(const ulonglong2*)(ar + 8);
        ulonglong2 aw3 = *(const ulonglong2*)(ar + 12);

        asm volatile("cp.async.wait_group 0;" ::: "memory");
        __syncthreads();   // barA: z_s[buf] staged; prev agg + prev sw reads closed

        // prefetch next tile into the other buffer
        if (tile < 15) {
            const float* s2 = gsrc + (size_t)(tile + 1) * 4096;
            uint32_t dsh = buf ? zshA : zshB;
            #pragma unroll
            for (int j = 0; j < 4; j++) cp16(dsh + j * 16, s2 + 4 * j);
            asm volatile("cp.async.commit_group;" ::: "memory");
        }

        // ---- stats (all 4 row-threads end with full sums in regs) ----
        float mz, rz, et;
        {
            const float* zr = &zc[srow * 68 + sc0];
            ulonglong2 aws[4] = {aw0, aw1, aw2, aw3};
            u64 zs2 = 0, zq2 = 0, xs2 = 0, xq2 = 0, xu2 = 0;
            #pragma unroll
            for (int j = 0; j < 4; j++) {
                ulonglong2 zw = *(const ulonglong2*)(zr + 4 * j);
                ulonglong2 uw = *(const ulonglong2*)(&sm_uq[sc0 + 4 * j]);
                zs2 = add2(zs2, zw.x); zq2 = fma2(zw.x, zw.x, zq2);
                u64 xa = add2(zw.x, aws[j].x);
                xs2 = add2(xs2, xa); xq2 = fma2(xa, xa, xq2); xu2 = fma2(xa, uw.x, xu2);
                zs2 = add2(zs2, zw.y); zq2 = fma2(zw.y, zw.y, zq2);
                u64 xb = add2(zw.y, aws[j].y);
                xs2 = add2(xs2, xb); xq2 = fma2(xb, xb, xq2); xu2 = fma2(xb, uw.y, xu2);
            }
            float zs = hadd2(zs2), zq = hadd2(zq2);
            float xs = hadd2(xs2), xq = hadd2(xq2), xu = hadd2(xu2);
            #pragma unroll
            for (int m = 1; m < 4; m <<= 1) {
                zs += __shfl_xor_sync(~0u, zs, m);
                zq += __shfl_xor_sync(~0u, zq, m);
                xs += __shfl_xor_sync(~0u, xs, m);
                xq += __shfl_xor_sync(~0u, xq, m);
                xu += __shfl_xor_sync(~0u, xu, m);
            }
            mz = zs * (1.f / 64.f);
            float vz = zq * (1.f / 64.f) - mz * mz;
            rz = rsqrtf(vz + EPSV);
            float mx = xs * (1.f / 64.f);
            float vx = xq * (1.f / 64.f) - mx * mx;
            float st = SCALEV * (rsqrtf(vx + EPSV) * (xu - mx * su));
            et = __expf(st);   // |st| LN-bounded; safe without max-sub
        }

        // ---- scoresK GEMM: own row x 4 ks ----
        u64 aa0 = 0, aa1 = 0, aa2 = 0, aa3 = 0;
        {
            const float* zrow = &zc[srow * 68];
            #pragma unroll
            for (int d4 = 0; d4 < 16; d4++) {
                ulonglong2 zp = *(const ulonglong2*)(zrow + d4 * 4);
                ulonglong2 g0 = *(const ulonglong2*)&gp_s[(k4 + 0) * 68 + d4 * 4];
                ulonglong2 g1 = *(const ulonglong2*)&gp_s[(k4 + 1) * 68 + d4 * 4];
                ulonglong2 g2 = *(const ulonglong2*)&gp_s[(k4 + 2) * 68 + d4 * 4];
                ulonglong2 g3 = *(const ulonglong2*)&gp_s[(k4 + 3) * 68 + d4 * 4];
                aa0 = fma2(zp.x, g0.x, aa0); aa0 = fma2(zp.y, g0.y, aa0);
                aa1 = fma2(zp.x, g1.x, aa1); aa1 = fma2(zp.y, g1.y, aa1);
                aa2 = fma2(zp.x, g2.x, aa2); aa2 = fma2(zp.y, g2.y, aa2);
                aa3 = fma2(zp.x, g3.x, aa3); aa3 = fma2(zp.y, g3.y, aa3);
            }
        }

        // ---- softmaxK in-register (4-thread row group, masks 1,2) ----
        {
            float s0 = SCALEV * (rz * (hadd2(aa0) - mz * sgp4[0]) + ck4[0]);
            float s1 = SCALEV * (rz * (hadd2(aa1) - mz * sgp4[1]) + ck4[1]);
            float s2 = SCALEV * (rz * (hadd2(aa2) - mz * sgp4[2]) + ck4[2]);
            float s3 = SCALEV * (rz * (hadd2(aa3) - mz * sgp4[3]) + ck4[3]);
            float mx = fmaxf(fmaxf(s0, s1), fmaxf(s2, s3));
            mx = fmaxf(mx, __shfl_xor_sync(~0u, mx, 1));
            mx = fmaxf(mx, __shfl_xor_sync(~0u, mx, 2));
            float e0 = __expf(s0 - mx), e1 = __expf(s1 - mx);
            float e2 = __expf(s2 - mx), e3 = __expf(s3 - mx);
            float ss = e0 + e1 + e2 + e3;
            ss += __shfl_xor_sync(~0u, ss, 1);
            ss += __shfl_xor_sync(~0u, ss, 2);
            float wf = et / ss;
            float w0 = e0 * wf, w1 = e1 * wf, w2 = e2 * wf, w3 = e3 * wf;
            *(float4*)&sw2[srow * 18 + k4]     = make_float4(w0, w0, w1, w1);
            *(float4*)&sw2[srow * 18 + k4 + 2] = make_float4(w2, w2, w3, w3);
            if ((tid & 3) == 0) S_part += et;
        }
        __syncthreads();   // barC: sw2 ready

        // ---- aggregation: 16 tokens, 4 k's x 4 d's, duplicated weights ----
        #pragma unroll
        for (int t0 = 0; t0 < 16; t0++) {
            int t = tcb + t0;
            ulonglong2 zp  = *(const ulonglong2*)&zc[t * 68 + dg4];
            ulonglong2 w01 = *(const ulonglong2*)&sw2[t * 18 + kg4];
            ulonglong2 w23 = *(const ulonglong2*)&sw2[t * 18 + kg4 + 2];
            acc[0][0] = fma2(zp.x, w01.x, acc[0][0]); acc[0][1] = fma2(zp.y, w01.x, acc[0][1]);
            acc[1][0] = fma2(zp.x, w01.y, acc[1][0]); acc[1][1] = fma2(zp.y, w01.y, acc[1][1]);
            acc[2][0] = fma2(zp.x, w23.x, acc[2][0]); acc[2][1] = fma2(zp.y, w23.x, acc[2][1]);
            acc[3][0] = fma2(zp.x, w23.y, acc[3][0]); acc[3][1] = fma2(zp.y, w23.y, acc[3][1]);
        }
        // next tile's wait + barA closes this phase
    }

    // ---- global denominator S ----
    #pragma unroll
    for (int m = 1; m < 32; m <<= 1) S_part += __shfl_xor_sync(~0u, S_part, m);
    if (lane == 0) atomicAdd(&sm_S, S_part);
    __syncthreads();   // S complete; agg done before reusing z_s[0]
    const float invS = 1.0f / sm_S;

    float* red = &z_s[0][0];
    {
        const int cb = (tid >> 6) * 1024;
        #pragma unroll
        for (int kk = 0; kk < 4; kk++) {
            float2 lo, hi;
            asm("mov.b64 {%0,%1},%2;":"=f"(lo.x),"=f"(lo.y):"l"(acc[kk][0]));
            asm("mov.b64 {%0,%1},%2;":"=f"(hi.x),"=f"(hi.y):"l"(acc[kk][1]));
            *(float4*)&red[cb + (kg4 + kk) * 64 + dg4] = make_float4(lo.x, lo.y, hi.x, hi.y);
        }
    }
    __syncthreads();

    // ---- final sum + beta_seq + LN + store ----
    {
        const int c4 = tid * 4;
        const int kk = tid >> 4;
        const int d0 = (tid & 15) * 4;
        float4 v0 = *(const float4*)&red[c4];
        float4 v1 = *(const float4*)&red[1024 + c4];
        float4 v2 = *(const float4*)&red[2048 + c4];
        float4 v3 = *(const float4*)&red[3072 + c4];
        float4 bs = *(const float4*)&beta_seq[c4];
        float o0 = (v0.x + v1.x + v2.x + v3.x) * invS + bs.x;
        float o1 = (v0.y + v1.y + v2.y + v3.y) * invS + bs.y;
        float o2 = (v0.z + v1.z + v2.z + v3.z) * invS + bs.z;
        float o3 = (v0.w + v1.w + v2.w + v3.w) * invS + bs.w;
        float s  = o0 + o1 + o2 + o3;
        float sq = o0 * o0 + o1 * o1 + o2 * o2 + o3 * o3;
        #pragma unroll
        for (int m = 8; m; m >>= 1) {
            s  += __shfl_xor_sync(~0u, s,  m);
            sq += __shfl_xor_sync(~0u, sq, m);
        }
        float mean = s * (1.f / 64.f);
        float var  = sq * (1.f / 64.f) - mean * mean;
        float r    = rsqrtf(var + EPSV);
        float4 g4 = *(const float4*)&gamma[4 * 64 + d0];
        float4 b4 = *(const float4*)&beta[4 * 64 + d0];
        float4 ov;
        ov.x = (o0 - mean) * r * g4.x + b4.x;
        ov.y = (o1 - mean) * r * g4.y + b4.y;
        ov.z = (o2 - mean) * r * g4.z + b4.z;
        ov.w = (o3 - mean) * r * g4.w + b4.w;
        *(float4*)&out[((size_t)b * 16 + kk) * 64 + d0] = ov;
    }
}

extern "C" void kernel_launch(void* const* d_in, const int* in_sizes, int n_in,
                              void* d_out, int out_size)
{
    const float* z        = (const float*)d_in[0];
    const float* prot     = (const float*)d_in[1];
    const float* alphas   = (const float*)d_in[2];
    const float* b_bias   = (const float*)d_in[3];
    const float* W        = (const float*)d_in[4];
    // d_in[5] = Wb: softmax-invariant constant, unused.
    const float* gamma    = (const float*)d_in[6];
    const float* beta     = (const float*)d_in[7];
    const float* beta_seq = (const float*)d_in[8];
    float* out = (float*)d_out;

    const int T = in_sizes[2] / 64;
    const int B = in_sizes[0] / (T * 64);

    setup_kernel<<<1, 512>>>(prot, gamma, beta);
    dse_main_kernel<<<B, 256>>>(z, alphas, b_bias, W, gamma, beta, beta_seq, out);
}

// round 15
// speedup vs baseline: 1.6625x; 1.6625x over previous
#include <cuda_runtime.h>
#include <math.h>
#include <float.h>
#include <stdint.h>

#define EPSV 1e-6f
#define SCALEV 0.125f

typedef unsigned long long u64;

__device__ __forceinline__ u64 fma2(u64 a, u64 b, u64 c){ u64 d; asm("fma.rn.f32x2 %0,%1,%2,%3;":"=l"(d):"l"(a),"l"(b),"l"(c)); return d; }
__device__ __forceinline__ u64 add2(u64 a, u64 b){ u64 d; asm("add.rn.f32x2 %0,%1,%2;":"=l"(d):"l"(a),"l"(b)); return d; }
__device__ __forceinline__ u64 pack2(float x, float y){ u64 d; asm("mov.b64 %0,{%1,%2};":"=l"(d):"f"(x),"f"(y)); return d; }
__device__ __forceinline__ float hadd2(u64 a){ float x,y; asm("mov.b64 {%0,%1},%2;":"=f"(x),"=f"(y):"l"(a)); return x+y; }
__device__ __forceinline__ void cp16(uint32_t dst, const void* src){
    asm volatile("cp.async.cg.shared.global [%0], [%1], 16;" :: "r"(dst), "l"(src));
}

__device__ float d_gp[16 * 64];
__device__ float d_sgp[16];
__device__ float d_ck[16];

__global__ void setup_kernel(const float* __restrict__ prot,
                             const float* __restrict__ gamma,
                             const float* __restrict__ beta)
{
    int w = threadIdx.x >> 5;
    int l = threadIdx.x & 31;
    if (w >= 16) return;
    const float* g0 = gamma;       const float* b0 = beta;
    const float* g1 = gamma + 64;  const float* b1 = beta + 64;

    float p0 = prot[w * 64 + l];
    float p1 = prot[w * 64 + l + 32];
    float s = p0 + p1, q = p0 * p0 + p1 * p1;
    #pragma unroll
    for (int m = 16; m; m >>= 1) {
        s += __shfl_xor_sync(~0u, s, m);
        q += __shfl_xor_sync(~0u, q, m);
    }
    float mean = s * (1.f / 64.f);
    float var  = q * (1.f / 64.f) - mean * mean;
    float r    = rsqrtf(var + EPSV);
    float pn0 = (p0 - mean) * r * g1[l]      + b1[l];
    float pn1 = (p1 - mean) * r * g1[l + 32] + b1[l + 32];
    float gp0 = g0[l] * pn0;
    float gp1 = g0[l + 32] * pn1;
    d_gp[w * 64 + l]      = gp0;
    d_gp[w * 64 + l + 32] = gp1;
    float sg  = gp0 + gp1;
    float ckp = b0[l] * pn0 + b0[l + 32] * pn1;
    #pragma unroll
    for (int m = 16; m; m >>= 1) {
        sg  += __shfl_xor_sync(~0u, sg, m);
        ckp += __shfl_xor_sync(~0u, ckp, m);
    }
    if (l == 0) { d_sgp[w] = sg; d_ck[w] = ckp; }
}

// Phases per tile (3 barriers):
//   barA: z tile staged. stats (4-thread row groups -> regs) + scoresK GEMM
//         (k=tid&15, tl=tid>>4 -> sraw[row][k])
//   barB: sraw visible. softmaxK by row groups (stats from regs), write sw
//   barC: sw visible. aggregation.
__global__ __launch_bounds__(256, 4)
void dse_main_kernel(const float* __restrict__ z,
                     const float* __restrict__ alphas,
                     const float* __restrict__ b_bias,
                     const float* __restrict__ W,
                     const float* __restrict__ gamma,
                     const float* __restrict__ beta,
                     const float* __restrict__ beta_seq,
                     float* __restrict__ out)
{
    __shared__ __align__(16) float z_s[2][64 * 68];   // 34816 B
    __shared__ __align__(16) float sw[64 * 16];       //  4096 B (weights)
    __shared__ __align__(16) float sraw[64 * 16];     //  4096 B (raw dots)
    __shared__ __align__(16) float gp_s[16 * 68];     //  4352 B
    __shared__ __align__(16) float sm_uq[64];         // q then u
    __shared__ __align__(16) float sm_sgp[16];
    __shared__ __align__(16) float sm_ck[16];
    __shared__ float sm_S;

    const int tid  = threadIdx.x;
    const int lane = tid & 31;
    const int wid  = tid >> 5;
    const int b    = blockIdx.x;
    const size_t zb = (size_t)b * (1024 * 64);

    const int srow = tid >> 2;            // stats/softmax row
    const int sc0  = (tid & 3) * 16;      // stats quarter
    const int k4   = (tid & 3) * 4;       // softmax k-quad

    const uint32_t zshA = (uint32_t)__cvta_generic_to_shared(&z_s[0][srow * 68 + sc0]);
    const uint32_t zshB = (uint32_t)__cvta_generic_to_shared(&z_s[1][srow * 68 + sc0]);
    const float* gsrc = z + zb + (size_t)srow * 64 + sc0;
    const float* asrc = alphas + (size_t)srow * 64 + sc0;

    // tile 0 fetch
    #pragma unroll
    for (int j = 0; j < 4; j++) cp16(zshA + j * 16, gsrc + 4 * j);
    asm volatile("cp.async.commit_group;" ::: "memory");

    // ---- prologue ----
    if (wid == 0) {
        const float* g3 = gamma + 3 * 64;
        const float* b3 = beta  + 3 * 64;
        const float* g2 = gamma + 2 * 64;
        const int d1 = lane, d2 = lane + 32;
        float x1 = alphas[1023 * 64 + d1] + z[zb + 1023 * 64 + d1] + b_bias[d1];
        float x2 = alphas[1023 * 64 + d2] + z[zb + 1023 * 64 + d2] + b_bias[d2];
        float s = x1 + x2, sq = x1 * x1 + x2 * x2;
        #pragma unroll
        for (int m = 16; m; m >>= 1) {
            s  += __shfl_xor_sync(~0u, s,  m);
            sq += __shfl_xor_sync(~0u, sq, m);
        }
        float mean = s * (1.f / 64.f);
        float var  = sq * (1.f / 64.f) - mean * mean;
        float r    = rsqrtf(var + EPSV);
        float q1 = (x1 - mean) * r * g3[d1] + b3[d1];
        float q2 = (x2 - mean) * r * g3[d2] + b3[d2];
        sm_uq[d1] = q1; sm_uq[d2] = q2;
        __syncwarp();
        float wq1 = 0.f, wq2 = 0.f;
        #pragma unroll 4
        for (int e4 = 0; e4 < 16; e4++) {
            float4 qv = *(const float4*)&sm_uq[e4 * 4];
            float4 w1 = *(const float4*)(W + d1 * 64 + e4 * 4);
            float4 w2 = *(const float4*)(W + d2 * 64 + e4 * 4);
            wq1 += w1.x * qv.x + w1.y * qv.y + w1.z * qv.z + w1.w * qv.w;
            wq2 += w2.x * qv.x + w2.y * qv.y + w2.z * qv.z + w2.w * qv.w;
        }
        __syncwarp();   // all lanes done reading q before overwriting with u
        float u1 = g2[d1] * (q1 + wq1);
        float u2 = g2[d2] * (q2 + wq2);
        sm_uq[d1] = u1; sm_uq[d2] = u2;
    } else {
        for (int i = tid - 32; i < 256; i += 224) {
            int row = i >> 4, c4 = (i & 15) * 4;
            *(float4*)&gp_s[row * 68 + c4] = *(const float4*)&d_gp[row * 64 + c4];
        }
        if (tid >= 32 && tid < 48) sm_sgp[tid - 32] = d_sgp[tid - 32];
        if (tid >= 48 && tid < 64) sm_ck[tid - 48]  = d_ck[tid - 48];
        if (tid == 64) sm_S = 0.f;
    }
    __syncthreads();

    // su = sum(u): 16 x 4-float smem reads
    float su;
    {
        u64 s2 = 0;
        #pragma unroll
        for (int j = 0; j < 16; j++) {
            ulonglong2 uw = *(const ulonglong2*)&sm_uq[j * 4];
            s2 = add2(s2, uw.x); s2 = add2(s2, uw.y);
        }
        su = hadd2(s2);
    }

    // GEMM mapping
    const int k  = tid & 15;
    const int tl = tid >> 4;
    // aggregation mapping
    const int idx  = tid & 63;
    const int dg4  = (idx & 15) * 4;
    const int kg4  = (idx >> 4) * 4;
    const int tcb  = (tid >> 6) * 16;

    u64 acc[4][2] = {{0,0},{0,0},{0,0},{0,0}};
    float S_part = 0.f;

    #pragma unroll 1
    for (int tile = 0; tile < 16; tile++) {
        const int buf = tile & 1;
        const float* zc = z_s[buf];

        // alphas loads (issued before cp wait; consumed in stats)
        const float* ar = asrc + (size_t)tile * 4096;
        ulonglong2 aw0 = *(const ulonglong2*)(ar);
        ulonglong2 aw1 = *(const ulonglong2*)(ar + 4);
        ulonglong2 aw2 = *(const ulonglong2*)(ar + 8);
        ulonglong2 aw3 = *(const ulonglong2*)(ar + 12);

        asm volatile("cp.async.wait_group 0;" ::: "memory");
        __syncthreads();   // barA

        // prefetch next tile
        if (tile < 15) {
            const float* s2 = gsrc + (size_t)(tile + 1) * 4096;
            uint32_t dsh = buf ? zshA : zshB;
            #pragma unroll
            for (int j = 0; j < 4; j++) cp16(dsh + j * 16, s2 + 4 * j);
            asm volatile("cp.async.commit_group;" ::: "memory");
        }

        // ---- stats for row srow (result in regs of all 4 group threads) ----
        float mz, rz, et;
        {
            const float* zr = &zc[srow * 68 + sc0];
            ulonglong2 aws[4] = {aw0, aw1, aw2, aw3};
            u64 zs2 = 0, zq2 = 0, xs2 = 0, xq2 = 0, xu2 = 0;
            #pragma unroll
            for (int j = 0; j < 4; j++) {
                ulonglong2 zw = *(const ulonglong2*)(zr + 4 * j);
                ulonglong2 uw = *(const ulonglong2*)(&sm_uq[sc0 + 4 * j]);
                zs2 = add2(zs2, zw.x); zq2 = fma2(zw.x, zw.x, zq2);
                u64 xa = add2(zw.x, aws[j].x);
                xs2 = add2(xs2, xa); xq2 = fma2(xa, xa, xq2); xu2 = fma2(xa, uw.x, xu2);
                zs2 = add2(zs2, zw.y); zq2 = fma2(zw.y, zw.y, zq2);
                u64 xb = add2(zw.y, aws[j].y);
                xs2 = add2(xs2, xb); xq2 = fma2(xb, xb, xq2); xu2 = fma2(xb, uw.y, xu2);
            }
            float zs = hadd2(zs2), zq = hadd2(zq2);
            float xs = hadd2(xs2), xq = hadd2(xq2), xu = hadd2(xu2);
            #pragma unroll
            for (int m = 1; m < 4; m <<= 1) {
                zs += __shfl_xor_sync(~0u, zs, m);
                zq += __shfl_xor_sync(~0u, zq, m);
                xs += __shfl_xor_sync(~0u, xs, m);
                xq += __shfl_xor_sync(~0u, xq, m);
                xu += __shfl_xor_sync(~0u, xu, m);
            }
            mz = zs * (1.f / 64.f);
            float vz = zq * (1.f / 64.f) - mz * mz;
            rz = rsqrtf(vz + EPSV);
            float mx = xs * (1.f / 64.f);
            float vx = xq * (1.f / 64.f) - mx * mx;
            float st = SCALEV * (rsqrtf(vx + EPSV) * (xu - mx * su));
            et = __expf(st);   // |st| LN-bounded; safe without max-sub
        }

        // ---- scoresK GEMM: 1 gp row x 4 z rows; raw dots -> sraw ----
        {
            u64 aa0 = 0, aa1 = 0, aa2 = 0, aa3 = 0;
            #pragma unroll
            for (int d4 = 0; d4 < 16; d4++) {
                ulonglong2 g  = *(const ulonglong2*)&gp_s[k * 68 + d4 * 4];
                ulonglong2 z0 = *(const ulonglong2*)&zc[tl * 68 + d4 * 4];
                ulonglong2 z1 = *(const ulonglong2*)&zc[(tl + 16) * 68 + d4 * 4];
                ulonglong2 z2 = *(const ulonglong2*)&zc[(tl + 32) * 68 + d4 * 4];
                ulonglong2 z3 = *(const ulonglong2*)&zc[(tl + 48) * 68 + d4 * 4];
                aa0 = fma2(z0.x, g.x, aa0); aa0 = fma2(z0.y, g.y, aa0);
                aa1 = fma2(z1.x, g.x, aa1); aa1 = fma2(z1.y, g.y, aa1);
                aa2 = fma2(z2.x, g.x, aa2); aa2 = fma2(z2.y, g.y, aa2);
                aa3 = fma2(z3.x, g.x, aa3); aa3 = fma2(z3.y, g.y, aa3);
            }
            sraw[(tl +  0) * 16 + k] = hadd2(aa0);
            sraw[(tl + 16) * 16 + k] = hadd2(aa1);
            sraw[(tl + 32) * 16 + k] = hadd2(aa2);
            sraw[(tl + 48) * 16 + k] = hadd2(aa3);
        }
        __syncthreads();   // barB: sraw visible

        // ---- softmaxK: row srow, quad k4; stats already in regs ----
        {
            float4 rq  = *(const float4*)&sraw[srow * 16 + k4];
            float4 sg4 = *(const float4*)&sm_sgp[k4];
            float4 cc4 = *(const float4*)&sm_ck[k4];
            float s0 = SCALEV * (rz * (rq.x - mz * sg4.x) + cc4.x);
            float s1 = SCALEV * (rz * (rq.y - mz * sg4.y) + cc4.y);
            float s2 = SCALEV * (rz * (rq.z - mz * sg4.z) + cc4.z);
            float s3 = SCALEV * (rz * (rq.w - mz * sg4.w) + cc4.w);
            float mx = fmaxf(fmaxf(s0, s1), fmaxf(s2, s3));
            mx = fmaxf(mx, __shfl_xor_sync(~0u, mx, 1));
            mx = fmaxf(mx, __shfl_xor_sync(~0u, mx, 2));
            float e0 = __expf(s0 - mx), e1 = __expf(s1 - mx);
            float e2 = __expf(s2 - mx), e3 = __expf(s3 - mx);
            float ss = e0 + e1 + e2 + e3;
            ss += __shfl_xor_sync(~0u, ss, 1);
            ss += __shfl_xor_sync(~0u, ss, 2);
            float wf = et / ss;
            *(float4*)&sw[srow * 16 + k4] =
                make_float4(e0 * wf, e1 * wf, e2 * wf, e3 * wf);
            if ((tid & 3) == 0) S_part += et;
        }
        __syncthreads();   // barC: sw ready

        // ---- aggregation: 16 tokens, 4 k's x 4 d's ----
        #pragma unroll
        for (int t0 = 0; t0 < 16; t0++) {
            int t = tcb + t0;
            ulonglong2 zp = *(const ulonglong2*)&zc[t * 68 + dg4];
            float4 w4 = *(const float4*)&sw[t * 16 + kg4];
            u64 w0 = pack2(w4.x, w4.x), w1 = pack2(w4.y, w4.y);
            u64 w2 = pack2(w4.z, w4.z), w3 = pack2(w4.w, w4.w);
            acc[0][0] = fma2(zp.x, w0, acc[0][0]); acc[0][1] = fma2(zp.y, w0, acc[0][1]);
            acc[1][0] = fma2(zp.x, w1, acc[1][0]); acc[1][1] = fma2(zp.y, w1, acc[1][1]);
            acc[2][0] = fma2(zp.x, w2, acc[2][0]); acc[2][1] = fma2(zp.y, w2, acc[2][1]);
            acc[3][0] = fma2(zp.x, w3, acc[3][0]); acc[3][1] = fma2(zp.y, w3, acc[3][1]);
        }
        // next tile's wait + barA closes this phase
    }

    // ---- global denominator S ----
    #pragma unroll
    for (int m = 1; m < 32; m <<= 1) S_part += __shfl_xor_sync(~0u, S_part, m);
    if (lane == 0) atomicAdd(&sm_S, S_part);
    __syncthreads();   // S complete; agg done before reusing z_s[0]
    const float invS = 1.0f / sm_S;

    float* red = &z_s[0][0];
    {
        const int cb = (tid >> 6) * 1024;
        #pragma unroll
        for (int kk = 0; kk < 4; kk++) {
            float2 lo, hi;
            asm("mov.b64 {%0,%1},%2;":"=f"(lo.x),"=f"(lo.y):"l"(acc[kk][0]));
            asm("mov.b64 {%0,%1},%2;":"=f"(hi.x),"=f"(hi.y):"l"(acc[kk][1]));
            *(float4*)&red[cb + (kg4 + kk) * 64 + dg4] = make_float4(lo.x, lo.y, hi.x, hi.y);
        }
    }
    __syncthreads();

    // ---- final sum + beta_seq + LN + store ----
    {
        const int c4 = tid * 4;
        const int kk = tid >> 4;
        const int d0 = (tid & 15) * 4;
        float4 v0 = *(const float4*)&red[c4];
        float4 v1 = *(const float4*)&red[1024 + c4];
        float4 v2 = *(const float4*)&red[2048 + c4];
        float4 v3 = *(const float4*)&red[3072 + c4];
        float4 bs = *(const float4*)&beta_seq[c4];
        float o0 = (v0.x + v1.x + v2.x + v3.x) * invS + bs.x;
        float o1 = (v0.y + v1.y + v2.y + v3.y) * invS + bs.y;
        float o2 = (v0.z + v1.z + v2.z + v3.z) * invS + bs.z;
        float o3 = (v0.w + v1.w + v2.w + v3.w) * invS + bs.w;
        float s  = o0 + o1 + o2 + o3;
        float sq = o0 * o0 + o1 * o1 + o2 * o2 + o3 * o3;
        #pragma unroll
        for (int m = 8; m; m >>= 1) {
            s  += __shfl_xor_sync(~0u, s,  m);
            sq += __shfl_xor_sync(~0u, sq, m);
        }
        float mean = s * (1.f / 64.f);
        float var  = sq * (1.f / 64.f) - mean * mean;
        float r    = rsqrtf(var + EPSV);
        float4 g4 = *(const float4*)&gamma[4 * 64 + d0];
        float4 b4 = *(const float4*)&beta[4 * 64 + d0];
        float4 ov;
        ov.x = (o0 - mean) * r * g4.x + b4.x;
        ov.y = (o1 - mean) * r * g4.y + b4.y;
        ov.z = (o2 - mean) * r * g4.z + b4.z;
        ov.w = (o3 - mean) * r * g4.w + b4.w;
        *(float4*)&out[((size_t)b * 16 + kk) * 64 + d0] = ov;
    }
}

extern "C" void kernel_launch(void* const* d_in, const int* in_sizes, int n_in,
                              void* d_out, int out_size)
{
    const float* z        = (const float*)d_in[0];
    const float* prot     = (const float*)d_in[1];
    const float* alphas   = (const float*)d_in[2];
    const float* b_bias   = (const float*)d_in[3];
    const float* W        = (const float*)d_in[4];
    // d_in[5] = Wb: softmax-invariant constant, unused.
    const float* gamma    = (const float*)d_in[6];
    const float* beta     = (const float*)d_in[7];
    const float* beta_seq = (const float*)d_in[8];
    float* out = (float*)d_out;

    const int T = in_sizes[2] / 64;
    const int B = in_sizes[0] / (T * 64);

    setup_kernel<<<1, 512>>>(prot, gamma, beta);
    dse_main_kernel<<<B, 256>>>(z, alphas, b_bias, W, gamma, beta, beta_seq, out);
}